// round 14
// baseline (speedup 1.0000x reference)
#include <cuda_runtime.h>
#include <math_constants.h>

// GraphSAGE fused: masked-max aggregation + relu + concat + Linear.
// B=4, N=512, C=128, OUT=128, adj ~10% dense (0.0/1.0 floats).
//
// R14 = R13 with the scratch sizing fixed (32 KB: union of agg buffers
// [25.1 KB] and split-k partials [32 KB]). Changes vs R11 (12.8us):
//  - idxbuf holds PRE-SCALED uint byte offsets (j*512) instead of ushort
//    row ids: gather batch drops all unpack (16 ops) + IMAD addressing
//    (8 ops) for +1 LDS.128; addresses are base + offset IADDs.
//  - final split-k reduction vectorized (float2 bias/partials/out).
//  - GEMM identical to R11 (adjacent-col pairs, LDG.64 W, fma.rn.f32x2).

#define B_DIM 4
#define N_DIM 512
#define C_DIM 128
#define OUT_DIM 128
#define ROWS 8
#define THREADS 512
#define ROW_BYTES (C_DIM * 4)     // 512
#define SCRATCH_BYTES 32768

__global__ __launch_bounds__(THREADS, 2)
void graphsage_fused_kernel(const float* __restrict__ adj,
                            const float* __restrict__ feat,
                            const float* __restrict__ W,
                            const float* __restrict__ bias,
                            float* __restrict__ out)
{
    __shared__ __align__(16) float combT[2 * C_DIM][ROWS];   // 8 KB persistent
    __shared__ __align__(16) char scratch[SCRATCH_BYTES];    // 32 KB aliased

    float (*aggbuf)[2][C_DIM] = reinterpret_cast<float (*)[2][C_DIM]>(scratch);
    unsigned (*idxbuf)[264] =
        reinterpret_cast<unsigned (*)[264]>(scratch + 8192);
    float* ps = reinterpret_cast<float*>(scratch);   // [8][ROWS*OUT] partials

    const int tid  = threadIdx.x;
    const int warp = tid >> 5;
    const int lane = tid & 31;
    const int row  = warp >> 1;
    const int half = warp & 1;

    const int block_row0 = blockIdx.x * ROWS;
    const int grow = block_row0 + row;
    const int b = grow >> 9;
    const int i = grow & (N_DIM - 1);

    const float* __restrict__ fb = feat + (size_t)b * N_DIM * C_DIM;
    const char* __restrict__ fbl =
        reinterpret_cast<const char*>(fb) + lane * 16;   // per-lane base

    // ---------------- Phase 1a: compact neighbor offsets ----------------
    const float* __restrict__ adjrow =
        adj + ((size_t)b * N_DIM + i) * N_DIM + half * (N_DIM / 2);
    unsigned* __restrict__ myidx = idxbuf[warp];
    const unsigned lt = (1u << lane) - 1u;

    int total = 0;
    #pragma unroll
    for (int c = 0; c < N_DIM / 2; c += 128) {
        float4 a = reinterpret_cast<const float4*>(adjrow + c)[lane];
        const unsigned obase =
            (unsigned)(half * (N_DIM / 2) + c + 4 * lane) * ROW_BYTES;
        {
            unsigned m = __ballot_sync(0xffffffffu, a.x > 0.0f);
            if (a.x > 0.0f) myidx[total + __popc(m & lt)] = obase;
            total += __popc(m);
        }
        {
            unsigned m = __ballot_sync(0xffffffffu, a.y > 0.0f);
            if (a.y > 0.0f) myidx[total + __popc(m & lt)] = obase + ROW_BYTES;
            total += __popc(m);
        }
        {
            unsigned m = __ballot_sync(0xffffffffu, a.z > 0.0f);
            if (a.z > 0.0f) myidx[total + __popc(m & lt)] = obase + 2 * ROW_BYTES;
            total += __popc(m);
        }
        {
            unsigned m = __ballot_sync(0xffffffffu, a.w > 0.0f);
            if (a.w > 0.0f) myidx[total + __popc(m & lt)] = obase + 3 * ROW_BYTES;
            total += __popc(m);
        }
    }
    __syncwarp();

    // ---------------- Phase 1b: gather + running max, MLP=8 ----------------
    float4 acc0 = make_float4(-CUDART_INF_F, -CUDART_INF_F, -CUDART_INF_F, -CUDART_INF_F);
    float4 acc1 = acc0, acc2 = acc0, acc3 = acc0;

    if (total > 0) {
        const int padded = (total + 7) & ~7;
        unsigned lastv = myidx[total - 1];
        __syncwarp();
        if (lane < padded - total) myidx[total + lane] = lastv;
        __syncwarp();

        const uint4* __restrict__ ivec = reinterpret_cast<const uint4*>(myidx);
        for (int k = 0; k < padded; k += 8) {
            uint4 I = ivec[(k >> 2)];
            uint4 J = ivec[(k >> 2) + 1];

            float4 f0 = *reinterpret_cast<const float4*>(fbl + I.x);
            float4 f1 = *reinterpret_cast<const float4*>(fbl + I.y);
            float4 f2 = *reinterpret_cast<const float4*>(fbl + I.z);
            float4 f3 = *reinterpret_cast<const float4*>(fbl + I.w);
            float4 f4 = *reinterpret_cast<const float4*>(fbl + J.x);
            float4 f5 = *reinterpret_cast<const float4*>(fbl + J.y);
            float4 f6 = *reinterpret_cast<const float4*>(fbl + J.z);
            float4 f7 = *reinterpret_cast<const float4*>(fbl + J.w);

            acc0.x = fmaxf(acc0.x, f0.x); acc0.y = fmaxf(acc0.y, f0.y);
            acc0.z = fmaxf(acc0.z, f0.z); acc0.w = fmaxf(acc0.w, f0.w);
            acc1.x = fmaxf(acc1.x, f1.x); acc1.y = fmaxf(acc1.y, f1.y);
            acc1.z = fmaxf(acc1.z, f1.z); acc1.w = fmaxf(acc1.w, f1.w);
            acc2.x = fmaxf(acc2.x, f2.x); acc2.y = fmaxf(acc2.y, f2.y);
            acc2.z = fmaxf(acc2.z, f2.z); acc2.w = fmaxf(acc2.w, f2.w);
            acc3.x = fmaxf(acc3.x, f3.x); acc3.y = fmaxf(acc3.y, f3.y);
            acc3.z = fmaxf(acc3.z, f3.z); acc3.w = fmaxf(acc3.w, f3.w);

            acc0.x = fmaxf(acc0.x, f4.x); acc0.y = fmaxf(acc0.y, f4.y);
            acc0.z = fmaxf(acc0.z, f4.z); acc0.w = fmaxf(acc0.w, f4.w);
            acc1.x = fmaxf(acc1.x, f5.x); acc1.y = fmaxf(acc1.y, f5.y);
            acc1.z = fmaxf(acc1.z, f5.z); acc1.w = fmaxf(acc1.w, f5.w);
            acc2.x = fmaxf(acc2.x, f6.x); acc2.y = fmaxf(acc2.y, f6.y);
            acc2.z = fmaxf(acc2.z, f6.z); acc2.w = fmaxf(acc2.w, f6.w);
            acc3.x = fmaxf(acc3.x, f7.x); acc3.y = fmaxf(acc3.y, f7.y);
            acc3.z = fmaxf(acc3.z, f7.z); acc3.w = fmaxf(acc3.w, f7.w);
        }
    }

    float4 accA;
    accA.x = fmaxf(fmaxf(acc0.x, acc1.x), fmaxf(acc2.x, acc3.x));
    accA.y = fmaxf(fmaxf(acc0.y, acc1.y), fmaxf(acc2.y, acc3.y));
    accA.z = fmaxf(fmaxf(acc0.z, acc1.z), fmaxf(acc2.z, acc3.z));
    accA.w = fmaxf(fmaxf(acc0.w, acc1.w), fmaxf(acc2.w, acc3.w));
    reinterpret_cast<float4*>(&aggbuf[row][half][0])[lane] = accA;

    __syncthreads();

    // ---- Phase 1c: build combT (feature copy + combine halves + relu) ----
    {
        const int r  = tid & 7;
        const int c8 = tid >> 3;
        const int gr = block_row0 + r;
        const int rb = gr >> 9;
        const int ri = gr & (N_DIM - 1);
        const float* __restrict__ frow =
            feat + ((size_t)rb * N_DIM + ri) * C_DIM;
        #pragma unroll
        for (int j = 0; j < 2; ++j) {
            const int c = c8 + 64 * j;
            combT[c][r] = frow[c];
            combT[C_DIM + c][r] =
                fmaxf(0.0f, fmaxf(aggbuf[r][0][c], aggbuf[r][1][c]));
        }
    }
    __syncthreads();

    // ---------------- Phase 2: fused linear layer ----------------
    // thread t: op = (t&63)*2 -> cols (op, op+1); g = t>>6 (8-way k-split,
    // 32 k each). 8 rows x 2 adjacent cols; W pair = one LDG.64 per k.
    {
        const int op = (tid & 63) * 2;
        const int g  = tid >> 6;

        const float2* __restrict__ wp = reinterpret_cast<const float2*>(
            W + (size_t)(g * 32) * OUT_DIM + op);
        const float* __restrict__ cb = &combT[g * 32][0];

        unsigned long long a01_0 = 0ull, a23_0 = 0ull, a45_0 = 0ull, a67_0 = 0ull;
        unsigned long long a01_1 = 0ull, a23_1 = 0ull, a45_1 = 0ull, a67_1 = 0ull;

        #pragma unroll 8
        for (int k = 0; k < 32; ++k) {
            float2 w = wp[(size_t)k * (OUT_DIM / 2)];
            unsigned long long wpk0, wpk1;
            asm("mov.b64 %0, {%1, %1};" : "=l"(wpk0) : "f"(w.x));
            asm("mov.b64 %0, {%1, %1};" : "=l"(wpk1) : "f"(w.y));

            const double2 q0 = *reinterpret_cast<const double2*>(cb + k * 8);
            const double2 q1 = *reinterpret_cast<const double2*>(cb + k * 8 + 4);
            unsigned long long p01 = __double_as_longlong(q0.x);
            unsigned long long p23 = __double_as_longlong(q0.y);
            unsigned long long p45 = __double_as_longlong(q1.x);
            unsigned long long p67 = __double_as_longlong(q1.y);

            asm("fma.rn.f32x2 %0, %1, %2, %0;" : "+l"(a01_0) : "l"(p01), "l"(wpk0));
            asm("fma.rn.f32x2 %0, %1, %2, %0;" : "+l"(a23_0) : "l"(p23), "l"(wpk0));
            asm("fma.rn.f32x2 %0, %1, %2, %0;" : "+l"(a45_0) : "l"(p45), "l"(wpk0));
            asm("fma.rn.f32x2 %0, %1, %2, %0;" : "+l"(a67_0) : "l"(p67), "l"(wpk0));
            asm("fma.rn.f32x2 %0, %1, %2, %0;" : "+l"(a01_1) : "l"(p01), "l"(wpk1));
            asm("fma.rn.f32x2 %0, %1, %2, %0;" : "+l"(a23_1) : "l"(p23), "l"(wpk1));
            asm("fma.rn.f32x2 %0, %1, %2, %0;" : "+l"(a45_1) : "l"(p45), "l"(wpk1));
            asm("fma.rn.f32x2 %0, %1, %2, %0;" : "+l"(a67_1) : "l"(p67), "l"(wpk1));
        }

        float r0, r1, r2, r3, r4, r5, r6, r7;
        float s0, s1, s2, s3, s4, s5, s6, s7;
        asm("mov.b64 {%0, %1}, %2;" : "=f"(r0), "=f"(r1) : "l"(a01_0));
        asm("mov.b64 {%0, %1}, %2;" : "=f"(r2), "=f"(r3) : "l"(a23_0));
        asm("mov.b64 {%0, %1}, %2;" : "=f"(r4), "=f"(r5) : "l"(a45_0));
        asm("mov.b64 {%0, %1}, %2;" : "=f"(r6), "=f"(r7) : "l"(a67_0));
        asm("mov.b64 {%0, %1}, %2;" : "=f"(s0), "=f"(s1) : "l"(a01_1));
        asm("mov.b64 {%0, %1}, %2;" : "=f"(s2), "=f"(s3) : "l"(a23_1));
        asm("mov.b64 {%0, %1}, %2;" : "=f"(s4), "=f"(s5) : "l"(a45_1));
        asm("mov.b64 {%0, %1}, %2;" : "=f"(s6), "=f"(s7) : "l"(a67_1));

        // partials: ps[g][row*128 + op(+1)]
        float* p = ps + (size_t)g * (ROWS * OUT_DIM) + op;
        p[0 * OUT_DIM] = r0;  p[1 * OUT_DIM] = r1;
        p[2 * OUT_DIM] = r2;  p[3 * OUT_DIM] = r3;
        p[4 * OUT_DIM] = r4;  p[5 * OUT_DIM] = r5;
        p[6 * OUT_DIM] = r6;  p[7 * OUT_DIM] = r7;
        p[0 * OUT_DIM + 1] = s0;  p[1 * OUT_DIM + 1] = s1;
        p[2 * OUT_DIM + 1] = s2;  p[3 * OUT_DIM + 1] = s3;
        p[4 * OUT_DIM + 1] = s4;  p[5 * OUT_DIM + 1] = s5;
        p[6 * OUT_DIM + 1] = s6;  p[7 * OUT_DIM + 1] = s7;

        __syncthreads();

        // final reduction: 1024 outputs, 2 adjacent per thread (float2)
        {
            const int idx = tid * 2;                  // row*128 + o
            float2 sum = *reinterpret_cast<const float2*>(
                bias + (idx & (OUT_DIM - 1)));
            #pragma unroll
            for (int gg = 0; gg < 8; ++gg) {
                float2 v = *reinterpret_cast<const float2*>(
                    ps + (size_t)gg * (ROWS * OUT_DIM) + idx);
                sum.x += v.x;
                sum.y += v.y;
            }
            *reinterpret_cast<float2*>(
                out + (size_t)block_row0 * OUT_DIM + idx) = sum;
        }
    }
}

// compile-time layout guards
static_assert(SCRATCH_BYTES >= 8 * ROWS * OUT_DIM * 4,
              "scratch too small for split-k partials");
static_assert(SCRATCH_BYTES >= 8192 + 16 * 264 * 4,
              "scratch too small for aggregation buffers");

extern "C" void kernel_launch(void* const* d_in, const int* in_sizes, int n_in,
                              void* d_out, int out_size)
{
    (void)in_sizes; (void)n_in; (void)out_size;
    const float* adj  = (const float*)d_in[0];   // [B,N,N]
    const float* feat = (const float*)d_in[1];   // [B,N,C]
    const float* W    = (const float*)d_in[2];   // [2C,OUT]
    const float* bias = (const float*)d_in[3];   // [OUT]
    float* out        = (float*)d_out;           // [B,N,OUT]

    dim3 grid((B_DIM * N_DIM) / ROWS);   // 256
    dim3 block(THREADS);                 // 512
    graphsage_fused_kernel<<<grid, block>>>(adj, feat, W, bias, out);
}

// round 16
// speedup vs baseline: 1.0244x; 1.0244x over previous
#include <cuda_runtime.h>
#include <math_constants.h>

// GraphSAGE fused: masked-max aggregation + relu + concat + Linear.
// B=4, N=512, C=128, OUT=128, adj ~10% dense (0.0/1.0 floats).
//
// R16 = R15 with the adjacency chunk-count bug fixed: each warp scans
// HALF a row = 256 floats = 2 float4-chunks (R15 wrongly read 4).
// Changes vs R11 (best, 12.8us):
//  - both adjacency chunk loads issued upfront (MLP=2 vs serial).
//  - own-feature values for combT prefetched into registers before the
//    gather loop (their LDG latency hides under gathering).
//  - float2-vectorized final split-k reduction.
// GEMM identical to R11 (adjacent-col pairs, LDG.64 W, fma.rn.f32x2).

#define B_DIM 4
#define N_DIM 512
#define C_DIM 128
#define OUT_DIM 128
#define ROWS 8
#define THREADS 512

__global__ __launch_bounds__(THREADS, 2)
void graphsage_fused_kernel(const float* __restrict__ adj,
                            const float* __restrict__ feat,
                            const float* __restrict__ W,
                            const float* __restrict__ bias,
                            float* __restrict__ out)
{
    __shared__ __align__(16) float combT[2 * C_DIM][ROWS];   // 8 KB persistent
    __shared__ __align__(16) char scratch[32768];            // 32 KB aliased

    float (*aggbuf)[2][C_DIM] = reinterpret_cast<float (*)[2][C_DIM]>(scratch);
    unsigned short (*idxbuf)[264] =
        reinterpret_cast<unsigned short (*)[264]>(scratch + 8192);
    float* ps = reinterpret_cast<float*>(scratch);   // [8][ROWS*OUT] partials

    const int tid  = threadIdx.x;
    const int warp = tid >> 5;
    const int lane = tid & 31;
    const int row  = warp >> 1;
    const int half = warp & 1;

    const int block_row0 = blockIdx.x * ROWS;
    const int grow = block_row0 + row;
    const int b = grow >> 9;
    const int i = grow & (N_DIM - 1);

    const float* __restrict__ fb = feat + (size_t)b * N_DIM * C_DIM;

    // ---------------- Phase 1a: compact neighbor indices ----------------
    // both chunk loads issued upfront -> MLP=2 on the adjacency stream
    const float4* __restrict__ adjv = reinterpret_cast<const float4*>(
        adj + ((size_t)b * N_DIM + i) * N_DIM + half * (N_DIM / 2));
    float4 av0 = adjv[lane];        // floats [0,128)   of this half-row
    float4 av1 = adjv[lane + 32];   // floats [128,256) of this half-row

    // prefetch own-feature values for combT (consumed in phase 1c)
    float fmy0, fmy1;
    {
        const int r  = tid & 7;
        const int c8 = tid >> 3;
        const int gr = block_row0 + r;
        const int rb = gr >> 9;
        const int ri = gr & (N_DIM - 1);
        const float* __restrict__ frow =
            feat + ((size_t)rb * N_DIM + ri) * C_DIM;
        fmy0 = frow[c8];
        fmy1 = frow[c8 + 64];
    }

    unsigned short* __restrict__ myidx = idxbuf[warp];
    const unsigned lt = (1u << lane) - 1u;

    int total = 0;
    {
        float4 chunks[2] = {av0, av1};
        #pragma unroll
        for (int cc = 0; cc < 2; ++cc) {
            float4 a = chunks[cc];
            const int cbase = half * (N_DIM / 2) + cc * 128 + 4 * lane;
            {
                unsigned m = __ballot_sync(0xffffffffu, a.x > 0.0f);
                if (a.x > 0.0f) myidx[total + __popc(m & lt)] = (unsigned short)(cbase + 0);
                total += __popc(m);
            }
            {
                unsigned m = __ballot_sync(0xffffffffu, a.y > 0.0f);
                if (a.y > 0.0f) myidx[total + __popc(m & lt)] = (unsigned short)(cbase + 1);
                total += __popc(m);
            }
            {
                unsigned m = __ballot_sync(0xffffffffu, a.z > 0.0f);
                if (a.z > 0.0f) myidx[total + __popc(m & lt)] = (unsigned short)(cbase + 2);
                total += __popc(m);
            }
            {
                unsigned m = __ballot_sync(0xffffffffu, a.w > 0.0f);
                if (a.w > 0.0f) myidx[total + __popc(m & lt)] = (unsigned short)(cbase + 3);
                total += __popc(m);
            }
        }
    }
    __syncwarp();

    // ---------------- Phase 1b: gather + running max, MLP=8 ----------------
    float4 acc0 = make_float4(-CUDART_INF_F, -CUDART_INF_F, -CUDART_INF_F, -CUDART_INF_F);
    float4 acc1 = acc0, acc2 = acc0, acc3 = acc0;

    if (total > 0) {
        const int padded = (total + 7) & ~7;
        unsigned short lastv = myidx[total - 1];
        __syncwarp();
        if (lane < padded - total) myidx[total + lane] = lastv;
        __syncwarp();

        const uint4* __restrict__ ivec = reinterpret_cast<const uint4*>(myidx);
        for (int k = 0; k < padded; k += 8) {
            uint4 I = ivec[k >> 3];
            int j0 =  I.x        & 0xffff;
            int j1 = (I.x >> 16) & 0xffff;
            int j2 =  I.y        & 0xffff;
            int j3 = (I.y >> 16) & 0xffff;
            int j4 =  I.z        & 0xffff;
            int j5 = (I.z >> 16) & 0xffff;
            int j6 =  I.w        & 0xffff;
            int j7 = (I.w >> 16) & 0xffff;

            float4 f0 = reinterpret_cast<const float4*>(fb + (size_t)j0 * C_DIM)[lane];
            float4 f1 = reinterpret_cast<const float4*>(fb + (size_t)j1 * C_DIM)[lane];
            float4 f2 = reinterpret_cast<const float4*>(fb + (size_t)j2 * C_DIM)[lane];
            float4 f3 = reinterpret_cast<const float4*>(fb + (size_t)j3 * C_DIM)[lane];
            float4 f4 = reinterpret_cast<const float4*>(fb + (size_t)j4 * C_DIM)[lane];
            float4 f5 = reinterpret_cast<const float4*>(fb + (size_t)j5 * C_DIM)[lane];
            float4 f6 = reinterpret_cast<const float4*>(fb + (size_t)j6 * C_DIM)[lane];
            float4 f7 = reinterpret_cast<const float4*>(fb + (size_t)j7 * C_DIM)[lane];

            acc0.x = fmaxf(acc0.x, f0.x); acc0.y = fmaxf(acc0.y, f0.y);
            acc0.z = fmaxf(acc0.z, f0.z); acc0.w = fmaxf(acc0.w, f0.w);
            acc1.x = fmaxf(acc1.x, f1.x); acc1.y = fmaxf(acc1.y, f1.y);
            acc1.z = fmaxf(acc1.z, f1.z); acc1.w = fmaxf(acc1.w, f1.w);
            acc2.x = fmaxf(acc2.x, f2.x); acc2.y = fmaxf(acc2.y, f2.y);
            acc2.z = fmaxf(acc2.z, f2.z); acc2.w = fmaxf(acc2.w, f2.w);
            acc3.x = fmaxf(acc3.x, f3.x); acc3.y = fmaxf(acc3.y, f3.y);
            acc3.z = fmaxf(acc3.z, f3.z); acc3.w = fmaxf(acc3.w, f3.w);

            acc0.x = fmaxf(acc0.x, f4.x); acc0.y = fmaxf(acc0.y, f4.y);
            acc0.z = fmaxf(acc0.z, f4.z); acc0.w = fmaxf(acc0.w, f4.w);
            acc1.x = fmaxf(acc1.x, f5.x); acc1.y = fmaxf(acc1.y, f5.y);
            acc1.z = fmaxf(acc1.z, f5.z); acc1.w = fmaxf(acc1.w, f5.w);
            acc2.x = fmaxf(acc2.x, f6.x); acc2.y = fmaxf(acc2.y, f6.y);
            acc2.z = fmaxf(acc2.z, f6.z); acc2.w = fmaxf(acc2.w, f6.w);
            acc3.x = fmaxf(acc3.x, f7.x); acc3.y = fmaxf(acc3.y, f7.y);
            acc3.z = fmaxf(acc3.z, f7.z); acc3.w = fmaxf(acc3.w, f7.w);
        }
    }

    float4 accA;
    accA.x = fmaxf(fmaxf(acc0.x, acc1.x), fmaxf(acc2.x, acc3.x));
    accA.y = fmaxf(fmaxf(acc0.y, acc1.y), fmaxf(acc2.y, acc3.y));
    accA.z = fmaxf(fmaxf(acc0.z, acc1.z), fmaxf(acc2.z, acc3.z));
    accA.w = fmaxf(fmaxf(acc0.w, acc1.w), fmaxf(acc2.w, acc3.w));
    reinterpret_cast<float4*>(&aggbuf[row][half][0])[lane] = accA;

    __syncthreads();

    // ---- Phase 1c: build combT (prefetched feat + combine halves + relu) ----
    {
        const int r  = tid & 7;
        const int c8 = tid >> 3;
        combT[c8][r]       = fmy0;
        combT[c8 + 64][r]  = fmy1;
        combT[C_DIM + c8][r] =
            fmaxf(0.0f, fmaxf(aggbuf[r][0][c8], aggbuf[r][1][c8]));
        combT[C_DIM + c8 + 64][r] =
            fmaxf(0.0f, fmaxf(aggbuf[r][0][c8 + 64], aggbuf[r][1][c8 + 64]));
    }
    __syncthreads();

    // ---------------- Phase 2: fused linear layer ----------------
    // thread t: op = (t&63)*2 -> cols (op, op+1); g = t>>6 (8-way k-split,
    // 32 k each). 8 rows x 2 adjacent cols; W pair = one LDG.64 per k.
    {
        const int op = (tid & 63) * 2;
        const int g  = tid >> 6;

        const float2* __restrict__ wp = reinterpret_cast<const float2*>(
            W + (size_t)(g * 32) * OUT_DIM + op);
        const float* __restrict__ cb = &combT[g * 32][0];

        unsigned long long a01_0 = 0ull, a23_0 = 0ull, a45_0 = 0ull, a67_0 = 0ull;
        unsigned long long a01_1 = 0ull, a23_1 = 0ull, a45_1 = 0ull, a67_1 = 0ull;

        #pragma unroll 8
        for (int k = 0; k < 32; ++k) {
            float2 w = wp[(size_t)k * (OUT_DIM / 2)];
            unsigned long long wpk0, wpk1;
            asm("mov.b64 %0, {%1, %1};" : "=l"(wpk0) : "f"(w.x));
            asm("mov.b64 %0, {%1, %1};" : "=l"(wpk1) : "f"(w.y));

            const double2 q0 = *reinterpret_cast<const double2*>(cb + k * 8);
            const double2 q1 = *reinterpret_cast<const double2*>(cb + k * 8 + 4);
            unsigned long long p01 = __double_as_longlong(q0.x);
            unsigned long long p23 = __double_as_longlong(q0.y);
            unsigned long long p45 = __double_as_longlong(q1.x);
            unsigned long long p67 = __double_as_longlong(q1.y);

            asm("fma.rn.f32x2 %0, %1, %2, %0;" : "+l"(a01_0) : "l"(p01), "l"(wpk0));
            asm("fma.rn.f32x2 %0, %1, %2, %0;" : "+l"(a23_0) : "l"(p23), "l"(wpk0));
            asm("fma.rn.f32x2 %0, %1, %2, %0;" : "+l"(a45_0) : "l"(p45), "l"(wpk0));
            asm("fma.rn.f32x2 %0, %1, %2, %0;" : "+l"(a67_0) : "l"(p67), "l"(wpk0));
            asm("fma.rn.f32x2 %0, %1, %2, %0;" : "+l"(a01_1) : "l"(p01), "l"(wpk1));
            asm("fma.rn.f32x2 %0, %1, %2, %0;" : "+l"(a23_1) : "l"(p23), "l"(wpk1));
            asm("fma.rn.f32x2 %0, %1, %2, %0;" : "+l"(a45_1) : "l"(p45), "l"(wpk1));
            asm("fma.rn.f32x2 %0, %1, %2, %0;" : "+l"(a67_1) : "l"(p67), "l"(wpk1));
        }

        float r0, r1, r2, r3, r4, r5, r6, r7;
        float s0, s1, s2, s3, s4, s5, s6, s7;
        asm("mov.b64 {%0, %1}, %2;" : "=f"(r0), "=f"(r1) : "l"(a01_0));
        asm("mov.b64 {%0, %1}, %2;" : "=f"(r2), "=f"(r3) : "l"(a23_0));
        asm("mov.b64 {%0, %1}, %2;" : "=f"(r4), "=f"(r5) : "l"(a45_0));
        asm("mov.b64 {%0, %1}, %2;" : "=f"(r6), "=f"(r7) : "l"(a67_0));
        asm("mov.b64 {%0, %1}, %2;" : "=f"(s0), "=f"(s1) : "l"(a01_1));
        asm("mov.b64 {%0, %1}, %2;" : "=f"(s2), "=f"(s3) : "l"(a23_1));
        asm("mov.b64 {%0, %1}, %2;" : "=f"(s4), "=f"(s5) : "l"(a45_1));
        asm("mov.b64 {%0, %1}, %2;" : "=f"(s6), "=f"(s7) : "l"(a67_1));

        // partials: ps[g][row*128 + op(+1)]
        float* p = ps + (size_t)g * (ROWS * OUT_DIM) + op;
        p[0 * OUT_DIM] = r0;  p[1 * OUT_DIM] = r1;
        p[2 * OUT_DIM] = r2;  p[3 * OUT_DIM] = r3;
        p[4 * OUT_DIM] = r4;  p[5 * OUT_DIM] = r5;
        p[6 * OUT_DIM] = r6;  p[7 * OUT_DIM] = r7;
        p[0 * OUT_DIM + 1] = s0;  p[1 * OUT_DIM + 1] = s1;
        p[2 * OUT_DIM + 1] = s2;  p[3 * OUT_DIM + 1] = s3;
        p[4 * OUT_DIM + 1] = s4;  p[5 * OUT_DIM + 1] = s5;
        p[6 * OUT_DIM + 1] = s6;  p[7 * OUT_DIM + 1] = s7;

        __syncthreads();

        // final reduction: 1024 outputs, 2 adjacent per thread (float2)
        {
            const int idx = tid * 2;                  // row*128 + o
            float2 sum = *reinterpret_cast<const float2*>(
                bias + (idx & (OUT_DIM - 1)));
            #pragma unroll
            for (int gg = 0; gg < 8; ++gg) {
                float2 v = *reinterpret_cast<const float2*>(
                    ps + (size_t)gg * (ROWS * OUT_DIM) + idx);
                sum.x += v.x;
                sum.y += v.y;
            }
            *reinterpret_cast<float2*>(
                out + (size_t)block_row0 * OUT_DIM + idx) = sum;
        }
    }
}

// compile-time layout guards
static_assert(32768 >= 8 * ROWS * OUT_DIM * 4, "scratch too small for partials");
static_assert(32768 >= 8192 + 16 * 264 * 2, "scratch too small for agg buffers");

extern "C" void kernel_launch(void* const* d_in, const int* in_sizes, int n_in,
                              void* d_out, int out_size)
{
    (void)in_sizes; (void)n_in; (void)out_size;
    const float* adj  = (const float*)d_in[0];   // [B,N,N]
    const float* feat = (const float*)d_in[1];   // [B,N,C]
    const float* W    = (const float*)d_in[2];   // [2C,OUT]
    const float* bias = (const float*)d_in[3];   // [OUT]
    float* out        = (float*)d_out;           // [B,N,OUT]

    dim3 grid((B_DIM * N_DIM) / ROWS);   // 256
    dim3 block(THREADS);                 // 512
    graphsage_fused_kernel<<<grid, block>>>(adj, feat, W, bias, out);
}

// round 17
// speedup vs baseline: 1.0295x; 1.0049x over previous
#include <cuda_runtime.h>
#include <math_constants.h>

// GraphSAGE fused: masked-max aggregation + relu + concat + Linear.
// B=4, N=512, C=128, OUT=128, adj ~10% dense (0.0/1.0 floats).
//
// FINAL (= R11, measured best 12.77us):
//  - aggregation: 2 warps/row, ballot-compact neighbor indices into smem,
//    gather in batches of 8 independent LDG.128 (MLP=8) into 4 rotating
//    float4 max-accumulators; relu fused into the combine.
//  - GEMM: combT stored k-major [256][8]; each thread computes 8 rows x
//    2 ADJACENT cols (one LDG.64 per k for the W pair), 8-way k-split
//    (32 k/thread) so W is read exactly once per block; packed
//    fma.rn.f32x2 throughout; 32KB smem split-k reduction.
//  - smem aliased: agg buffers / idx buffers / split-k partials share
//    one 32KB scratch; 41KB total -> 2 blocks/SM, grid 256 = one wave.

#define B_DIM 4
#define N_DIM 512
#define C_DIM 128
#define OUT_DIM 128
#define ROWS 8
#define THREADS 512

__global__ __launch_bounds__(THREADS, 2)
void graphsage_fused_kernel(const float* __restrict__ adj,
                            const float* __restrict__ feat,
                            const float* __restrict__ W,
                            const float* __restrict__ bias,
                            float* __restrict__ out)
{
    __shared__ __align__(16) float combT[2 * C_DIM][ROWS];   // 8 KB persistent
    __shared__ __align__(16) char scratch[32768];            // 32 KB aliased

    float (*aggbuf)[2][C_DIM] = reinterpret_cast<float (*)[2][C_DIM]>(scratch);
    unsigned short (*idxbuf)[264] =
        reinterpret_cast<unsigned short (*)[264]>(scratch + 8192);
    float* ps = reinterpret_cast<float*>(scratch);   // [8][ROWS*OUT] partials

    const int tid  = threadIdx.x;
    const int warp = tid >> 5;
    const int lane = tid & 31;
    const int row  = warp >> 1;
    const int half = warp & 1;

    const int block_row0 = blockIdx.x * ROWS;
    const int grow = block_row0 + row;
    const int b = grow >> 9;
    const int i = grow & (N_DIM - 1);

    const float* __restrict__ fb = feat + (size_t)b * N_DIM * C_DIM;

    // ---------------- Phase 1a: compact neighbor indices ----------------
    const float* __restrict__ adjrow =
        adj + ((size_t)b * N_DIM + i) * N_DIM + half * (N_DIM / 2);
    unsigned short* __restrict__ myidx = idxbuf[warp];
    const unsigned lt = (1u << lane) - 1u;

    int total = 0;
    #pragma unroll
    for (int c = 0; c < N_DIM / 2; c += 128) {
        float4 a = reinterpret_cast<const float4*>(adjrow + c)[lane];
        const int cbase = half * (N_DIM / 2) + c + 4 * lane;
        {
            unsigned m = __ballot_sync(0xffffffffu, a.x > 0.0f);
            if (a.x > 0.0f) myidx[total + __popc(m & lt)] = (unsigned short)(cbase + 0);
            total += __popc(m);
        }
        {
            unsigned m = __ballot_sync(0xffffffffu, a.y > 0.0f);
            if (a.y > 0.0f) myidx[total + __popc(m & lt)] = (unsigned short)(cbase + 1);
            total += __popc(m);
        }
        {
            unsigned m = __ballot_sync(0xffffffffu, a.z > 0.0f);
            if (a.z > 0.0f) myidx[total + __popc(m & lt)] = (unsigned short)(cbase + 2);
            total += __popc(m);
        }
        {
            unsigned m = __ballot_sync(0xffffffffu, a.w > 0.0f);
            if (a.w > 0.0f) myidx[total + __popc(m & lt)] = (unsigned short)(cbase + 3);
            total += __popc(m);
        }
    }
    __syncwarp();

    // ---------------- Phase 1b: gather + running max, MLP=8 ----------------
    float4 acc0 = make_float4(-CUDART_INF_F, -CUDART_INF_F, -CUDART_INF_F, -CUDART_INF_F);
    float4 acc1 = acc0, acc2 = acc0, acc3 = acc0;

    if (total > 0) {
        const int padded = (total + 7) & ~7;
        unsigned short lastv = myidx[total - 1];
        __syncwarp();
        if (lane < padded - total) myidx[total + lane] = lastv;
        __syncwarp();

        const uint4* __restrict__ ivec = reinterpret_cast<const uint4*>(myidx);
        for (int k = 0; k < padded; k += 8) {
            uint4 I = ivec[k >> 3];
            int j0 =  I.x        & 0xffff;
            int j1 = (I.x >> 16) & 0xffff;
            int j2 =  I.y        & 0xffff;
            int j3 = (I.y >> 16) & 0xffff;
            int j4 =  I.z        & 0xffff;
            int j5 = (I.z >> 16) & 0xffff;
            int j6 =  I.w        & 0xffff;
            int j7 = (I.w >> 16) & 0xffff;

            float4 f0 = reinterpret_cast<const float4*>(fb + (size_t)j0 * C_DIM)[lane];
            float4 f1 = reinterpret_cast<const float4*>(fb + (size_t)j1 * C_DIM)[lane];
            float4 f2 = reinterpret_cast<const float4*>(fb + (size_t)j2 * C_DIM)[lane];
            float4 f3 = reinterpret_cast<const float4*>(fb + (size_t)j3 * C_DIM)[lane];
            float4 f4 = reinterpret_cast<const float4*>(fb + (size_t)j4 * C_DIM)[lane];
            float4 f5 = reinterpret_cast<const float4*>(fb + (size_t)j5 * C_DIM)[lane];
            float4 f6 = reinterpret_cast<const float4*>(fb + (size_t)j6 * C_DIM)[lane];
            float4 f7 = reinterpret_cast<const float4*>(fb + (size_t)j7 * C_DIM)[lane];

            acc0.x = fmaxf(acc0.x, f0.x); acc0.y = fmaxf(acc0.y, f0.y);
            acc0.z = fmaxf(acc0.z, f0.z); acc0.w = fmaxf(acc0.w, f0.w);
            acc1.x = fmaxf(acc1.x, f1.x); acc1.y = fmaxf(acc1.y, f1.y);
            acc1.z = fmaxf(acc1.z, f1.z); acc1.w = fmaxf(acc1.w, f1.w);
            acc2.x = fmaxf(acc2.x, f2.x); acc2.y = fmaxf(acc2.y, f2.y);
            acc2.z = fmaxf(acc2.z, f2.z); acc2.w = fmaxf(acc2.w, f2.w);
            acc3.x = fmaxf(acc3.x, f3.x); acc3.y = fmaxf(acc3.y, f3.y);
            acc3.z = fmaxf(acc3.z, f3.z); acc3.w = fmaxf(acc3.w, f3.w);

            acc0.x = fmaxf(acc0.x, f4.x); acc0.y = fmaxf(acc0.y, f4.y);
            acc0.z = fmaxf(acc0.z, f4.z); acc0.w = fmaxf(acc0.w, f4.w);
            acc1.x = fmaxf(acc1.x, f5.x); acc1.y = fmaxf(acc1.y, f5.y);
            acc1.z = fmaxf(acc1.z, f5.z); acc1.w = fmaxf(acc1.w, f5.w);
            acc2.x = fmaxf(acc2.x, f6.x); acc2.y = fmaxf(acc2.y, f6.y);
            acc2.z = fmaxf(acc2.z, f6.z); acc2.w = fmaxf(acc2.w, f6.w);
            acc3.x = fmaxf(acc3.x, f7.x); acc3.y = fmaxf(acc3.y, f7.y);
            acc3.z = fmaxf(acc3.z, f7.z); acc3.w = fmaxf(acc3.w, f7.w);
        }
    }

    float4 accA;
    accA.x = fmaxf(fmaxf(acc0.x, acc1.x), fmaxf(acc2.x, acc3.x));
    accA.y = fmaxf(fmaxf(acc0.y, acc1.y), fmaxf(acc2.y, acc3.y));
    accA.z = fmaxf(fmaxf(acc0.z, acc1.z), fmaxf(acc2.z, acc3.z));
    accA.w = fmaxf(fmaxf(acc0.w, acc1.w), fmaxf(acc2.w, acc3.w));
    reinterpret_cast<float4*>(&aggbuf[row][half][0])[lane] = accA;

    __syncthreads();

    // ---- Phase 1c: build combT (feature copy + combine halves + relu) ----
    {
        const int r  = tid & 7;
        const int c8 = tid >> 3;
        const int gr = block_row0 + r;
        const int rb = gr >> 9;
        const int ri = gr & (N_DIM - 1);
        const float* __restrict__ frow =
            feat + ((size_t)rb * N_DIM + ri) * C_DIM;
        #pragma unroll
        for (int j = 0; j < 2; ++j) {
            const int c = c8 + 64 * j;
            combT[c][r] = frow[c];
            combT[C_DIM + c][r] =
                fmaxf(0.0f, fmaxf(aggbuf[r][0][c], aggbuf[r][1][c]));
        }
    }
    __syncthreads();

    // ---------------- Phase 2: fused linear layer ----------------
    // thread t: op = (t&63)*2 -> cols (op, op+1); g = t>>6 (8-way k-split,
    // 32 k each). 8 rows x 2 adjacent cols; W pair = one LDG.64 per k.
    {
        const int op = (tid & 63) * 2;
        const int g  = tid >> 6;

        const float2* __restrict__ wp = reinterpret_cast<const float2*>(
            W + (size_t)(g * 32) * OUT_DIM + op);
        const float* __restrict__ cb = &combT[g * 32][0];

        unsigned long long a01_0 = 0ull, a23_0 = 0ull, a45_0 = 0ull, a67_0 = 0ull;
        unsigned long long a01_1 = 0ull, a23_1 = 0ull, a45_1 = 0ull, a67_1 = 0ull;

        #pragma unroll 8
        for (int k = 0; k < 32; ++k) {
            float2 w = wp[(size_t)k * (OUT_DIM / 2)];
            unsigned long long wpk0, wpk1;
            asm("mov.b64 %0, {%1, %1};" : "=l"(wpk0) : "f"(w.x));
            asm("mov.b64 %0, {%1, %1};" : "=l"(wpk1) : "f"(w.y));

            const double2 q0 = *reinterpret_cast<const double2*>(cb + k * 8);
            const double2 q1 = *reinterpret_cast<const double2*>(cb + k * 8 + 4);
            unsigned long long p01 = __double_as_longlong(q0.x);
            unsigned long long p23 = __double_as_longlong(q0.y);
            unsigned long long p45 = __double_as_longlong(q1.x);
            unsigned long long p67 = __double_as_longlong(q1.y);

            asm("fma.rn.f32x2 %0, %1, %2, %0;" : "+l"(a01_0) : "l"(p01), "l"(wpk0));
            asm("fma.rn.f32x2 %0, %1, %2, %0;" : "+l"(a23_0) : "l"(p23), "l"(wpk0));
            asm("fma.rn.f32x2 %0, %1, %2, %0;" : "+l"(a45_0) : "l"(p45), "l"(wpk0));
            asm("fma.rn.f32x2 %0, %1, %2, %0;" : "+l"(a67_0) : "l"(p67), "l"(wpk0));
            asm("fma.rn.f32x2 %0, %1, %2, %0;" : "+l"(a01_1) : "l"(p01), "l"(wpk1));
            asm("fma.rn.f32x2 %0, %1, %2, %0;" : "+l"(a23_1) : "l"(p23), "l"(wpk1));
            asm("fma.rn.f32x2 %0, %1, %2, %0;" : "+l"(a45_1) : "l"(p45), "l"(wpk1));
            asm("fma.rn.f32x2 %0, %1, %2, %0;" : "+l"(a67_1) : "l"(p67), "l"(wpk1));
        }

        float r0, r1, r2, r3, r4, r5, r6, r7;
        float s0, s1, s2, s3, s4, s5, s6, s7;
        asm("mov.b64 {%0, %1}, %2;" : "=f"(r0), "=f"(r1) : "l"(a01_0));
        asm("mov.b64 {%0, %1}, %2;" : "=f"(r2), "=f"(r3) : "l"(a23_0));
        asm("mov.b64 {%0, %1}, %2;" : "=f"(r4), "=f"(r5) : "l"(a45_0));
        asm("mov.b64 {%0, %1}, %2;" : "=f"(r6), "=f"(r7) : "l"(a67_0));
        asm("mov.b64 {%0, %1}, %2;" : "=f"(s0), "=f"(s1) : "l"(a01_1));
        asm("mov.b64 {%0, %1}, %2;" : "=f"(s2), "=f"(s3) : "l"(a23_1));
        asm("mov.b64 {%0, %1}, %2;" : "=f"(s4), "=f"(s5) : "l"(a45_1));
        asm("mov.b64 {%0, %1}, %2;" : "=f"(s6), "=f"(s7) : "l"(a67_1));

        // partials: ps[g][row*128 + op(+1)]
        float* p = ps + (size_t)g * (ROWS * OUT_DIM) + op;
        p[0 * OUT_DIM] = r0;  p[1 * OUT_DIM] = r1;
        p[2 * OUT_DIM] = r2;  p[3 * OUT_DIM] = r3;
        p[4 * OUT_DIM] = r4;  p[5 * OUT_DIM] = r5;
        p[6 * OUT_DIM] = r6;  p[7 * OUT_DIM] = r7;
        p[0 * OUT_DIM + 1] = s0;  p[1 * OUT_DIM + 1] = s1;
        p[2 * OUT_DIM + 1] = s2;  p[3 * OUT_DIM + 1] = s3;
        p[4 * OUT_DIM + 1] = s4;  p[5 * OUT_DIM + 1] = s5;
        p[6 * OUT_DIM + 1] = s6;  p[7 * OUT_DIM + 1] = s7;

        __syncthreads();

        // final reduction: 1024 outputs, 2 per thread
        #pragma unroll
        for (int rep = 0; rep < 2; ++rep) {
            const int idx = tid + rep * THREADS;      // row*128 + o
            float sum = bias[idx & (OUT_DIM - 1)];
            #pragma unroll
            for (int gg = 0; gg < 8; ++gg)
                sum += ps[(size_t)gg * (ROWS * OUT_DIM) + idx];
            out[(size_t)block_row0 * OUT_DIM + idx] = sum;
        }
    }
}

// compile-time layout guards
static_assert(32768 >= 8 * ROWS * OUT_DIM * 4, "scratch too small for partials");
static_assert(32768 >= 8192 + 16 * 264 * 2, "scratch too small for agg buffers");

extern "C" void kernel_launch(void* const* d_in, const int* in_sizes, int n_in,
                              void* d_out, int out_size)
{
    (void)in_sizes; (void)n_in; (void)out_size;
    const float* adj  = (const float*)d_in[0];   // [B,N,N]
    const float* feat = (const float*)d_in[1];   // [B,N,C]
    const float* W    = (const float*)d_in[2];   // [2C,OUT]
    const float* bias = (const float*)d_in[3];   // [OUT]
    float* out        = (float*)d_out;           // [B,N,OUT]

    dim3 grid((B_DIM * N_DIM) / ROWS);   // 256
    dim3 block(THREADS);                 // 512
    graphsage_fused_kernel<<<grid, block>>>(adj, feat, W, bias, out);
}